// round 2
// baseline (speedup 1.0000x reference)
#include <cuda_runtime.h>
#include <cuda_bf16.h>

#define M_TOT 16384      // BATCH * SEQ
#define K_DIM 2048       // IN_DIM
#define D_DIM 2048       // OUT_DIM
#define BASIS 64
#define EPSV  1e-5f

// Scratch (allocation-free rule: __device__ globals)
__device__ float g_tr[(size_t)M_TOT * D_DIM];   // transformed = x @ W^T   (128 MB)
__device__ float g_At[BASIS * D_DIM];           // Acoeff transposed: At[j][d]

typedef unsigned long long u64;

__device__ __forceinline__ u64 fma2(u64 a, u64 b, u64 c) {
    u64 d;
    asm("fma.rn.f32x2 %0, %1, %2, %3;" : "=l"(d) : "l"(a), "l"(b), "l"(c));
    return d;
}

// ---------------------------------------------------------------------------
// SGEMM: C[m][n] = sum_k A[m][k] * B[n][k]   (both operands K-major)
// 128x128x16 tiles, 256 threads, 8x8 per thread, packed f32x2 FMA.
// ---------------------------------------------------------------------------
__global__ void __launch_bounds__(256, 2)
sgemm_kernel(const float* __restrict__ A, const float* __restrict__ Bw,
             float* __restrict__ C) {
    __shared__ float2 As2[16][128];   // A value duplicated into both lanes
    __shared__ float  Bs[16][128];

    const int tid  = threadIdx.x;
    const int m0   = blockIdx.y * 128;
    const int n0   = blockIdx.x * 128;
    const int lrow = tid >> 1;            // 0..127
    const int lcol = (tid & 1) * 8;       // 0 or 8
    const int ty   = tid >> 4;            // 0..15 -> m sub-tile
    const int tx   = tid & 15;            // 0..15 -> n sub-tile

    const float* aptr = A  + (size_t)(m0 + lrow) * K_DIM + lcol;
    const float* bptr = Bw + (size_t)(n0 + lrow) * K_DIM + lcol;

    u64 acc[8][4];
#pragma unroll
    for (int i = 0; i < 8; i++)
#pragma unroll
        for (int j = 0; j < 4; j++) acc[i][j] = 0ull;

    for (int k0 = 0; k0 < K_DIM; k0 += 16) {
        float4 a0 = *(const float4*)(aptr);
        float4 a1 = *(const float4*)(aptr + 4);
        float4 b0 = *(const float4*)(bptr);
        float4 b1 = *(const float4*)(bptr + 4);
        aptr += 16; bptr += 16;

        __syncthreads();   // previous iter's readers done
        As2[lcol + 0][lrow] = make_float2(a0.x, a0.x);
        As2[lcol + 1][lrow] = make_float2(a0.y, a0.y);
        As2[lcol + 2][lrow] = make_float2(a0.z, a0.z);
        As2[lcol + 3][lrow] = make_float2(a0.w, a0.w);
        As2[lcol + 4][lrow] = make_float2(a1.x, a1.x);
        As2[lcol + 5][lrow] = make_float2(a1.y, a1.y);
        As2[lcol + 6][lrow] = make_float2(a1.z, a1.z);
        As2[lcol + 7][lrow] = make_float2(a1.w, a1.w);
        Bs[lcol + 0][lrow] = b0.x;
        Bs[lcol + 1][lrow] = b0.y;
        Bs[lcol + 2][lrow] = b0.z;
        Bs[lcol + 3][lrow] = b0.w;
        Bs[lcol + 4][lrow] = b1.x;
        Bs[lcol + 5][lrow] = b1.y;
        Bs[lcol + 6][lrow] = b1.z;
        Bs[lcol + 7][lrow] = b1.w;
        __syncthreads();

#pragma unroll
        for (int k = 0; k < 16; k++) {
            u64 a2[8], b2[4];
            const u64* ap = (const u64*)&As2[k][ty * 8];
            const u64* bp = (const u64*)&Bs[k][tx * 8];
#pragma unroll
            for (int i = 0; i < 8; i++) a2[i] = ap[i];
#pragma unroll
            for (int j = 0; j < 4; j++) b2[j] = bp[j];
#pragma unroll
            for (int i = 0; i < 8; i++)
#pragma unroll
                for (int j = 0; j < 4; j++)
                    acc[i][j] = fma2(a2[i], b2[j], acc[i][j]);
        }
    }

#pragma unroll
    for (int i = 0; i < 8; i++) {
        float* crow = C + (size_t)(m0 + ty * 8 + i) * D_DIM + n0 + tx * 8;
#pragma unroll
        for (int j = 0; j < 4; j++) {
            float2 v;
            v.x = __uint_as_float((unsigned)(acc[i][j] & 0xffffffffull));
            v.y = __uint_as_float((unsigned)(acc[i][j] >> 32));
            *(float2*)(crow + 2 * j) = v;
        }
    }
}

// ---------------------------------------------------------------------------
// Transpose Acoeff [D][BASIS] -> At [BASIS][D] so the epilogue is coalesced.
// ---------------------------------------------------------------------------
__global__ void transposeA_kernel(const float* __restrict__ Acoeff) {
    int idx = blockIdx.x * blockDim.x + threadIdx.x;
    if (idx < D_DIM * BASIS) {
        int d = idx / BASIS, j = idx % BASIS;
        g_At[j * D_DIM + d] = Acoeff[idx];
    }
}

// ---------------------------------------------------------------------------
// Block reduce (256 threads, 8 warps)
// ---------------------------------------------------------------------------
__device__ __forceinline__ float blockReduce(float v) {
    __shared__ float sh[8];
#pragma unroll
    for (int o = 16; o > 0; o >>= 1) v += __shfl_xor_sync(0xffffffffu, v, o);
    int lane = threadIdx.x & 31, w = threadIdx.x >> 5;
    __syncthreads();                 // protect sh across calls
    if (lane == 0) sh[w] = v;
    __syncthreads();
    float tot = 0.f;
#pragma unroll
    for (int i = 0; i < 8; i++) tot += sh[i];
    return tot;
}

// ---------------------------------------------------------------------------
// Per-row: LayerNorm(transformed) -> scalar = <norm, B[j]> -> out += scalar*At[j]
// out already holds residual (x @ W_res^T). One block per row, 256 threads,
// 8 elements per thread (2048 = 256*8).
// ---------------------------------------------------------------------------
__global__ void __launch_bounds__(256)
ln_epilogue_kernel(const float* __restrict__ gamma, const float* __restrict__ beta,
                   const float* __restrict__ Bb, float* __restrict__ out) {
    const int r = blockIdx.x;
    const int j = r & (BASIS - 1);         // (r % 4096) % 64 == r % 64
    const int tid = threadIdx.x;
    const int c0 = tid * 8;

    const float* trow = g_tr + (size_t)r * D_DIM + c0;
    float4 t0 = *(const float4*)(trow);
    float4 t1 = *(const float4*)(trow + 4);
    float v[8] = {t0.x, t0.y, t0.z, t0.w, t1.x, t1.y, t1.z, t1.w};

    float s = 0.f, s2 = 0.f;
#pragma unroll
    for (int i = 0; i < 8; i++) { s += v[i]; s2 += v[i] * v[i]; }
    s  = blockReduce(s);
    s2 = blockReduce(s2);
    const float mean = s * (1.0f / D_DIM);
    const float var  = s2 * (1.0f / D_DIM) - mean * mean;
    const float inv  = rsqrtf(var + EPSV);

    float4 g0 = *(const float4*)(gamma + c0);
    float4 g1 = *(const float4*)(gamma + c0 + 4);
    float4 be0 = *(const float4*)(beta + c0);
    float4 be1 = *(const float4*)(beta + c0 + 4);
    const float* brow = Bb + j * D_DIM + c0;
    float4 B0 = *(const float4*)(brow);
    float4 B1 = *(const float4*)(brow + 4);
    float gg[8] = {g0.x, g0.y, g0.z, g0.w, g1.x, g1.y, g1.z, g1.w};
    float bb[8] = {be0.x, be0.y, be0.z, be0.w, be1.x, be1.y, be1.z, be1.w};
    float Bv[8] = {B0.x, B0.y, B0.z, B0.w, B1.x, B1.y, B1.z, B1.w};

    float part = 0.f;
#pragma unroll
    for (int i = 0; i < 8; i++)
        part += ((v[i] - mean) * inv * gg[i] + bb[i]) * Bv[i];
    const float scalar = blockReduce(part);

    const float* arow = g_At + j * D_DIM + c0;
    float4 A0 = *(const float4*)(arow);
    float4 A1 = *(const float4*)(arow + 4);
    float* orow = out + (size_t)r * D_DIM + c0;
    float4 o0 = *(const float4*)(orow);
    float4 o1 = *(const float4*)(orow + 4);
    o0.x += scalar * A0.x;  o0.y += scalar * A0.y;
    o0.z += scalar * A0.z;  o0.w += scalar * A0.w;
    o1.x += scalar * A1.x;  o1.y += scalar * A1.y;
    o1.z += scalar * A1.z;  o1.w += scalar * A1.w;
    *(float4*)(orow)     = o0;
    *(float4*)(orow + 4) = o1;
}

// ---------------------------------------------------------------------------
extern "C" void kernel_launch(void* const* d_in, const int* in_sizes, int n_in,
                              void* d_out, int out_size) {
    const float* x      = (const float*)d_in[0];
    const float* W      = (const float*)d_in[1];
    const float* W_res  = (const float*)d_in[2];
    const float* gamma  = (const float*)d_in[3];
    const float* beta   = (const float*)d_in[4];
    const float* Acoeff = (const float*)d_in[5];
    const float* Bbasis = (const float*)d_in[6];
    float* out = (float*)d_out;

    float* tr = nullptr;
    cudaGetSymbolAddress((void**)&tr, g_tr);

    dim3 grid(D_DIM / 128, M_TOT / 128);
    sgemm_kernel<<<grid, 256>>>(x, W, tr);        // transformed -> scratch
    sgemm_kernel<<<grid, 256>>>(x, W_res, out);   // residual    -> d_out
    transposeA_kernel<<<(D_DIM * BASIS + 255) / 256, 256>>>(Acoeff);
    ln_epilogue_kernel<<<M_TOT, 256>>>(gamma, beta, Bbasis, out);
}

// round 4
// speedup vs baseline: 3.4700x; 3.4700x over previous
#include <cuda_runtime.h>
#include <cuda_bf16.h>
#include <cstdint>

#define M_TOT 16384
#define K_DIM 2048
#define D_DIM 2048
#define BASIS 64
#define EPSV  1e-5f

#define KC     (3 * K_DIM)     // 6144 concatenated K
#define BM     128
#define BN     256
#define BK     64
#define STAGES 3
#define NKT    (KC / BK)       // 96

// ---------------- scratch (__device__ globals; no allocs allowed) -----------
__device__ float          g_tr[(size_t)M_TOT * D_DIM];        // transformed (128MB)
__device__ float          g_At[BASIS * D_DIM];
__device__ __nv_bfloat16  g_xcat[(size_t)M_TOT * KC];         // [hi | hi | lo] 192MB
__device__ __nv_bfloat16  g_wcat[(size_t)D_DIM * KC];         // [hi | lo | hi] 24MB
__device__ __nv_bfloat16  g_rcat[(size_t)D_DIM * KC];         // [hi | lo | hi] 24MB

// ---------------- PTX helpers ----------------------------------------------
__device__ __forceinline__ uint32_t smem_u32(const void* p) {
    uint32_t a;
    asm("{ .reg .u64 t; cvta.to.shared.u64 t, %1; cvt.u32.u64 %0, t; }" : "=r"(a) : "l"(p));
    return a;
}
__device__ __forceinline__ void cp_async16(uint32_t dst, const void* src) {
    asm volatile("cp.async.cg.shared.global [%0], [%1], 16;" :: "r"(dst), "l"(src));
}
__device__ __forceinline__ void cp_commit() {
    asm volatile("cp.async.commit_group;" ::: "memory");
}
template <int N>
__device__ __forceinline__ void cp_wait() {
    asm volatile("cp.async.wait_group %0;" :: "n"(N) : "memory");
}
__device__ __forceinline__ void ldsm4(uint32_t& r0, uint32_t& r1, uint32_t& r2,
                                      uint32_t& r3, uint32_t addr) {
    asm volatile("ldmatrix.sync.aligned.m8n8.x4.shared.b16 {%0,%1,%2,%3}, [%4];"
                 : "=r"(r0), "=r"(r1), "=r"(r2), "=r"(r3) : "r"(addr));
}
__device__ __forceinline__ void mma16816(float* d, uint32_t a0, uint32_t a1,
                                         uint32_t a2, uint32_t a3,
                                         uint32_t b0, uint32_t b1) {
    asm volatile("mma.sync.aligned.m16n8k16.row.col.f32.bf16.bf16.f32 "
                 "{%0,%1,%2,%3}, {%4,%5,%6,%7}, {%8,%9}, {%0,%1,%2,%3};"
                 : "+f"(d[0]), "+f"(d[1]), "+f"(d[2]), "+f"(d[3])
                 : "r"(a0), "r"(a1), "r"(a2), "r"(a3), "r"(b0), "r"(b1));
}

// SMEM: per stage A tile 128x64 bf16 (16KB) + B tile 256x64 bf16 (32KB)
#define STAGE_BYTES (BM * 128 + BN * 128)      // 49152
#define SM_TOTAL    (STAGES * STAGE_BYTES)     // 147456

// ---------------------------------------------------------------------------
// bf16 GEMM: C[m][n] = sum_k A[m][k] * B[n][k], A:[M_TOT][KC], B:[D_DIM][KC]
// ---------------------------------------------------------------------------
__global__ void __launch_bounds__(256, 1)
gemm_mma_kernel(const __nv_bfloat16* __restrict__ A,
                const __nv_bfloat16* __restrict__ B,
                float* __restrict__ C) {
    extern __shared__ char smem[];
    const uint32_t sb = smem_u32(smem);
    const int tid  = threadIdx.x;
    const int wid  = tid >> 5;
    const int lane = tid & 31;
    const int wm   = wid >> 2;           // 0..1  (64 rows each)
    const int wn   = wid & 3;            // 0..3  (64 cols each)
    const int m0   = blockIdx.y * BM;
    const int n0   = blockIdx.x * BN;

    // load-index precompute: A rows by seg>>3, chunk seg&7
    auto load_stage = [&](int stage, int kt) {
        const uint32_t base = sb + stage * STAGE_BYTES;
        const int kb = kt * BK;
#pragma unroll
        for (int i = 0; i < 4; i++) {            // A: 1024 segs
            int seg = tid + i * 256;
            int r = seg >> 3, ch = seg & 7;
            const __nv_bfloat16* src = A + (size_t)(m0 + r) * KC + kb + ch * 8;
            uint32_t dst = base + r * 128 + ((ch ^ (r & 7)) << 4);
            cp_async16(dst, src);
        }
#pragma unroll
        for (int i = 0; i < 8; i++) {            // B: 2048 segs
            int seg = tid + i * 256;
            int r = seg >> 3, ch = seg & 7;
            const __nv_bfloat16* src = B + (size_t)(n0 + r) * KC + kb + ch * 8;
            uint32_t dst = base + BM * 128 + r * 128 + ((ch ^ (r & 7)) << 4);
            cp_async16(dst, src);
        }
        cp_commit();
    };

    float acc[4][8][4];
#pragma unroll
    for (int i = 0; i < 4; i++)
#pragma unroll
        for (int j = 0; j < 8; j++)
#pragma unroll
            for (int q = 0; q < 4; q++) acc[i][j][q] = 0.f;

#pragma unroll
    for (int s = 0; s < STAGES - 1; s++) load_stage(s, s);

    for (int kt = 0; kt < NKT; kt++) {
        cp_wait<STAGES - 2>();
        __syncthreads();

        // prefetch next tile first
        int tn = kt + STAGES - 1;
        if (tn < NKT) load_stage(tn % STAGES, tn);
        else          cp_commit();

        const uint32_t stA = sb + (kt % STAGES) * STAGE_BYTES;
        const uint32_t stB = stA + BM * 128;

#pragma unroll
        for (int s = 0; s < 4; s++) {            // 4 k16 steps
            uint32_t a[4][4];
#pragma unroll
            for (int mt = 0; mt < 4; mt++) {
                int r  = wm * 64 + mt * 16 + (lane & 15);
                int ch = 2 * s + (lane >> 4);
                ldsm4(a[mt][0], a[mt][1], a[mt][2], a[mt][3],
                      stA + r * 128 + ((ch ^ (r & 7)) << 4));
            }
            uint32_t b[4][4];
#pragma unroll
            for (int nt = 0; nt < 4; nt++) {
                int r  = wn * 64 + nt * 16 + (lane & 7) + ((lane >> 4) << 3);
                int ch = 2 * s + ((lane >> 3) & 1);
                ldsm4(b[nt][0], b[nt][1], b[nt][2], b[nt][3],
                      stB + r * 128 + ((ch ^ (r & 7)) << 4));
            }
#pragma unroll
            for (int mt = 0; mt < 4; mt++)
#pragma unroll
                for (int nt = 0; nt < 4; nt++) {
                    mma16816(acc[mt][2 * nt],     a[mt][0], a[mt][1], a[mt][2], a[mt][3],
                             b[nt][0], b[nt][1]);
                    mma16816(acc[mt][2 * nt + 1], a[mt][0], a[mt][1], a[mt][2], a[mt][3],
                             b[nt][2], b[nt][3]);
                }
        }
        __syncthreads();
    }

    // store C
#pragma unroll
    for (int mt = 0; mt < 4; mt++) {
        int row = m0 + wm * 64 + mt * 16 + (lane >> 2);
        int col0 = n0 + wn * 64 + (lane & 3) * 2;
#pragma unroll
        for (int j = 0; j < 8; j++) {
            float2 lo = make_float2(acc[mt][j][0], acc[mt][j][1]);
            float2 hi = make_float2(acc[mt][j][2], acc[mt][j][3]);
            *(float2*)(C + (size_t)row * D_DIM + col0 + j * 8)       = lo;
            *(float2*)(C + (size_t)(row + 8) * D_DIM + col0 + j * 8) = hi;
        }
    }
}

// ---------------------------------------------------------------------------
// fp32 -> concatenated bf16 split. mode 0: [hi|hi|lo] (x). mode 1: [hi|lo|hi].
// ---------------------------------------------------------------------------
template <int MODE>
__global__ void __launch_bounds__(256)
splitcat_kernel(const float* __restrict__ src, __nv_bfloat16* __restrict__ dst, int n4) {
    int i = blockIdx.x * blockDim.x + threadIdx.x;
    if (i >= n4) return;
    int row  = i / (K_DIM / 4);
    int col4 = i % (K_DIM / 4);
    float4 v = ((const float4*)src)[i];
    __nv_bfloat16 h[4] = {__float2bfloat16(v.x), __float2bfloat16(v.y),
                          __float2bfloat16(v.z), __float2bfloat16(v.w)};
    __nv_bfloat16 l[4] = {__float2bfloat16(v.x - __bfloat162float(h[0])),
                          __float2bfloat16(v.y - __bfloat162float(h[1])),
                          __float2bfloat16(v.z - __bfloat162float(h[2])),
                          __float2bfloat16(v.w - __bfloat162float(h[3]))};
    uint2 hv = *(uint2*)h;
    uint2 lv = *(uint2*)l;
    __nv_bfloat16* rp = dst + (size_t)row * KC + col4 * 4;
    if (MODE == 0) {           // x: [hi | hi | lo]
        *(uint2*)(rp)              = hv;
        *(uint2*)(rp + K_DIM)      = hv;
        *(uint2*)(rp + 2 * K_DIM)  = lv;
    } else {                   // w: [hi | lo | hi]
        *(uint2*)(rp)              = hv;
        *(uint2*)(rp + K_DIM)      = lv;
        *(uint2*)(rp + 2 * K_DIM)  = hv;
    }
}

// ---------------------------------------------------------------------------
__global__ void transposeA_kernel(const float* __restrict__ Acoeff) {
    int idx = blockIdx.x * blockDim.x + threadIdx.x;
    if (idx < D_DIM * BASIS) {
        int d = idx / BASIS, j = idx % BASIS;
        g_At[j * D_DIM + d] = Acoeff[idx];
    }
}

__device__ __forceinline__ float blockReduce(float v) {
    __shared__ float sh[8];
#pragma unroll
    for (int o = 16; o > 0; o >>= 1) v += __shfl_xor_sync(0xffffffffu, v, o);
    int lane = threadIdx.x & 31, w = threadIdx.x >> 5;
    __syncthreads();
    if (lane == 0) sh[w] = v;
    __syncthreads();
    float tot = 0.f;
#pragma unroll
    for (int i = 0; i < 8; i++) tot += sh[i];
    return tot;
}

__global__ void __launch_bounds__(256)
ln_epilogue_kernel(const float* __restrict__ gamma, const float* __restrict__ beta,
                   const float* __restrict__ Bb, float* __restrict__ out) {
    const int r = blockIdx.x;
    const int j = r & (BASIS - 1);
    const int tid = threadIdx.x;
    const int c0 = tid * 8;

    const float* trow = g_tr + (size_t)r * D_DIM + c0;
    float4 t0 = *(const float4*)(trow);
    float4 t1 = *(const float4*)(trow + 4);
    float v[8] = {t0.x, t0.y, t0.z, t0.w, t1.x, t1.y, t1.z, t1.w};

    float s = 0.f, s2 = 0.f;
#pragma unroll
    for (int i = 0; i < 8; i++) { s += v[i]; s2 += v[i] * v[i]; }
    s  = blockReduce(s);
    s2 = blockReduce(s2);
    const float mean = s * (1.0f / D_DIM);
    const float var  = s2 * (1.0f / D_DIM) - mean * mean;
    const float inv  = rsqrtf(var + EPSV);

    float4 g0 = *(const float4*)(gamma + c0);
    float4 g1 = *(const float4*)(gamma + c0 + 4);
    float4 be0 = *(const float4*)(beta + c0);
    float4 be1 = *(const float4*)(beta + c0 + 4);
    const float* brow = Bb + j * D_DIM + c0;
    float4 B0 = *(const float4*)(brow);
    float4 B1 = *(const float4*)(brow + 4);
    float gg[8] = {g0.x, g0.y, g0.z, g0.w, g1.x, g1.y, g1.z, g1.w};
    float bb[8] = {be0.x, be0.y, be0.z, be0.w, be1.x, be1.y, be1.z, be1.w};
    float Bv[8] = {B0.x, B0.y, B0.z, B0.w, B1.x, B1.y, B1.z, B1.w};

    float part = 0.f;
#pragma unroll
    for (int i = 0; i < 8; i++)
        part += ((v[i] - mean) * inv * gg[i] + bb[i]) * Bv[i];
    const float scalar = blockReduce(part);

    const float* arow = g_At + j * D_DIM + c0;
    float4 A0 = *(const float4*)(arow);
    float4 A1 = *(const float4*)(arow + 4);
    float* orow = out + (size_t)r * D_DIM + c0;
    float4 o0 = *(const float4*)(orow);
    float4 o1 = *(const float4*)(orow + 4);
    o0.x += scalar * A0.x;  o0.y += scalar * A0.y;
    o0.z += scalar * A0.z;  o0.w += scalar * A0.w;
    o1.x += scalar * A1.x;  o1.y += scalar * A1.y;
    o1.z += scalar * A1.z;  o1.w += scalar * A1.w;
    *(float4*)(orow)     = o0;
    *(float4*)(orow + 4) = o1;
}

// ---------------------------------------------------------------------------
extern "C" void kernel_launch(void* const* d_in, const int* in_sizes, int n_in,
                              void* d_out, int out_size) {
    const float* x      = (const float*)d_in[0];
    const float* W      = (const float*)d_in[1];
    const float* W_res  = (const float*)d_in[2];
    const float* gamma  = (const float*)d_in[3];
    const float* beta   = (const float*)d_in[4];
    const float* Acoeff = (const float*)d_in[5];
    const float* Bbasis = (const float*)d_in[6];
    float* out = (float*)d_out;

    float *tr;            cudaGetSymbolAddress((void**)&tr,   g_tr);
    __nv_bfloat16 *xcat;  cudaGetSymbolAddress((void**)&xcat, g_xcat);
    __nv_bfloat16 *wcat;  cudaGetSymbolAddress((void**)&wcat, g_wcat);
    __nv_bfloat16 *rcat;  cudaGetSymbolAddress((void**)&rcat, g_rcat);

    cudaFuncSetAttribute(gemm_mma_kernel,
                         cudaFuncAttributeMaxDynamicSharedMemorySize, SM_TOTAL);

    int nx4 = (M_TOT * K_DIM) / 4;
    int nw4 = (D_DIM * K_DIM) / 4;
    splitcat_kernel<0><<<(nx4 + 255) / 256, 256>>>(x, xcat, nx4);
    splitcat_kernel<1><<<(nw4 + 255) / 256, 256>>>(W, wcat, nw4);
    splitcat_kernel<1><<<(nw4 + 255) / 256, 256>>>(W_res, rcat, nw4);

    dim3 grid(D_DIM / BN, M_TOT / BM);    // (8, 128)
    gemm_mma_kernel<<<grid, 256, SM_TOTAL>>>(xcat, wcat, tr);
    gemm_mma_kernel<<<grid, 256, SM_TOTAL>>>(xcat, rcat, out);

    transposeA_kernel<<<(D_DIM * BASIS + 255) / 256, 256>>>(Acoeff);
    ln_epilogue_kernel<<<M_TOT, 256>>>(gamma, beta, Bbasis, out);
}

// round 5
// speedup vs baseline: 5.0033x; 1.4419x over previous
#include <cuda_runtime.h>
#include <cuda_fp16.h>
#include <cstdint>

#define M_TOT 16384
#define K_DIM 2048
#define D_DIM 2048
#define BASIS 64
#define EPSV  1e-5f

#define KC     (2 * K_DIM)     // B-side K: [hi | lo]
#define BM     128
#define BN     256
#define BK     64
#define STAGES 3
#define NKT    (KC / BK)       // 64
#define NTHR   512

// ---------------- scratch (__device__ globals) ------------------------------
__device__ __half g_xh[(size_t)M_TOT * K_DIM];   // 64MB
__device__ __half g_ws[(size_t)D_DIM * KC];      // 16MB  [hi | lo]
__device__ __half g_rs[(size_t)D_DIM * KC];      // 16MB
__device__ float  g_At[BASIS * D_DIM];
__device__ float  g_gb[BASIS * D_DIM];           // gamma[d]*B[j][d]
__device__ float  g_c1[BASIS], g_c2[BASIS];
__device__ float  g_sum[M_TOT], g_sum2[M_TOT], g_dotb[M_TOT], g_scalar[M_TOT];

// ---------------- PTX helpers ----------------------------------------------
__device__ __forceinline__ uint32_t smem_u32(const void* p) {
    uint32_t a;
    asm("{ .reg .u64 t; cvta.to.shared.u64 t, %1; cvt.u32.u64 %0, t; }" : "=r"(a) : "l"(p));
    return a;
}
__device__ __forceinline__ void cp_async16(uint32_t dst, const void* src) {
    asm volatile("cp.async.cg.shared.global [%0], [%1], 16;" :: "r"(dst), "l"(src));
}
__device__ __forceinline__ void cp_commit() {
    asm volatile("cp.async.commit_group;" ::: "memory");
}
template <int N>
__device__ __forceinline__ void cp_wait() {
    asm volatile("cp.async.wait_group %0;" :: "n"(N) : "memory");
}
__device__ __forceinline__ void ldsm4(uint32_t& r0, uint32_t& r1, uint32_t& r2,
                                      uint32_t& r3, uint32_t addr) {
    asm volatile("ldmatrix.sync.aligned.m8n8.x4.shared.b16 {%0,%1,%2,%3}, [%4];"
                 : "=r"(r0), "=r"(r1), "=r"(r2), "=r"(r3) : "r"(addr));
}
__device__ __forceinline__ void mma16816(float* d, uint32_t a0, uint32_t a1,
                                         uint32_t a2, uint32_t a3,
                                         uint32_t b0, uint32_t b1) {
    asm volatile("mma.sync.aligned.m16n8k16.row.col.f32.f16.f16.f32 "
                 "{%0,%1,%2,%3}, {%4,%5,%6,%7}, {%8,%9}, {%0,%1,%2,%3};"
                 : "+f"(d[0]), "+f"(d[1]), "+f"(d[2]), "+f"(d[3])
                 : "r"(a0), "r"(a1), "r"(a2), "r"(a3), "r"(b0), "r"(b1));
}

#define STAGE_BYTES (BM * 128 + BN * 128)           // 49152
#define SM_STATS    (STAGES * STAGE_BYTES)          // stats region offset
#define SM_TOTAL    (STAGES * STAGE_BYTES + 1536)   // + 128 rows * 3 floats

// ---------------------------------------------------------------------------
// Fused dual GEMM. blockIdx.x<8: transformed path -> per-row LN partials only.
// blockIdx.x>=8: residual path -> store to out.
// A = x (fp16), K indexed mod 2048; B = [w_hi | w_lo], K = 4096.
// ---------------------------------------------------------------------------
__global__ void __launch_bounds__(NTHR, 1)
gemm_fused_kernel(const __half* __restrict__ X,
                  const __half* __restrict__ Wh,
                  const __half* __restrict__ Rh,
                  float* __restrict__ out) {
    extern __shared__ char smem[];
    const uint32_t sb = smem_u32(smem);
    float* sst = (float*)(smem + SM_STATS);
    const int tid  = threadIdx.x;
    const int wid  = tid >> 5;
    const int lane = tid & 31;
    const int wm   = wid >> 3;           // 0..1
    const int wn   = wid & 7;            // 0..7
    const int m0   = blockIdx.y * BM;
    const int bsel = blockIdx.x >> 3;    // 0 = W (stats), 1 = W_res (store)
    const int n0   = (blockIdx.x & 7) * BN;
    const __half* Bmat = bsel ? Rh : Wh;

    if (tid < 384) sst[tid] = 0.f;       // first syncthreads is in iter 0

    auto load_stage = [&](int stage, int kt) {
        const uint32_t base = sb + stage * STAGE_BYTES;
        const int kbA = (kt * BK) & (K_DIM - 1);
        const int kbB = kt * BK;
#pragma unroll
        for (int i = 0; i < 2; i++) {            // A: 1024 segs
            int seg = tid + i * NTHR;
            int r = seg >> 3, ch = seg & 7;
            cp_async16(base + r * 128 + ((ch ^ (r & 7)) << 4),
                       X + (size_t)(m0 + r) * K_DIM + kbA + ch * 8);
        }
#pragma unroll
        for (int i = 0; i < 4; i++) {            // B: 2048 segs
            int seg = tid + i * NTHR;
            int r = seg >> 3, ch = seg & 7;
            cp_async16(base + BM * 128 + r * 128 + ((ch ^ (r & 7)) << 4),
                       Bmat + (size_t)(n0 + r) * KC + kbB + ch * 8);
        }
        cp_commit();
    };

    float acc[4][4][4];
#pragma unroll
    for (int i = 0; i < 4; i++)
#pragma unroll
        for (int j = 0; j < 4; j++)
#pragma unroll
            for (int q = 0; q < 4; q++) acc[i][j][q] = 0.f;

#pragma unroll
    for (int s = 0; s < STAGES - 1; s++) load_stage(s, s);

    for (int kt = 0; kt < NKT; kt++) {
        cp_wait<STAGES - 2>();
        __syncthreads();

        int tn = kt + STAGES - 1;
        if (tn < NKT) load_stage(tn % STAGES, tn);
        else          cp_commit();

        const uint32_t stA = sb + (kt % STAGES) * STAGE_BYTES;
        const uint32_t stB = stA + BM * 128;

#pragma unroll
        for (int s = 0; s < 4; s++) {
            uint32_t a[4][4];
#pragma unroll
            for (int mt = 0; mt < 4; mt++) {
                int r  = wm * 64 + mt * 16 + (lane & 15);
                int ch = 2 * s + (lane >> 4);
                ldsm4(a[mt][0], a[mt][1], a[mt][2], a[mt][3],
                      stA + r * 128 + ((ch ^ (r & 7)) << 4));
            }
            uint32_t b[2][4];
#pragma unroll
            for (int nt = 0; nt < 2; nt++) {
                int r  = wn * 32 + nt * 16 + (lane & 7) + ((lane >> 4) << 3);
                int ch = 2 * s + ((lane >> 3) & 1);
                ldsm4(b[nt][0], b[nt][1], b[nt][2], b[nt][3],
                      stB + r * 128 + ((ch ^ (r & 7)) << 4));
            }
#pragma unroll
            for (int mt = 0; mt < 4; mt++)
#pragma unroll
                for (int nt = 0; nt < 2; nt++) {
                    mma16816(acc[mt][2 * nt],     a[mt][0], a[mt][1], a[mt][2], a[mt][3],
                             b[nt][0], b[nt][1]);
                    mma16816(acc[mt][2 * nt + 1], a[mt][0], a[mt][1], a[mt][2], a[mt][3],
                             b[nt][2], b[nt][3]);
                }
        }
        __syncthreads();
    }

    if (bsel == 1) {
        // residual path: store tile to out
#pragma unroll
        for (int mt = 0; mt < 4; mt++) {
            int row  = m0 + wm * 64 + mt * 16 + (lane >> 2);
            int col0 = n0 + wn * 32 + (lane & 3) * 2;
#pragma unroll
            for (int j = 0; j < 4; j++) {
                *(float2*)(out + (size_t)row * D_DIM + col0 + j * 8) =
                    make_float2(acc[mt][j][0], acc[mt][j][1]);
                *(float2*)(out + (size_t)(row + 8) * D_DIM + col0 + j * 8) =
                    make_float2(acc[mt][j][2], acc[mt][j][3]);
            }
        }
    } else {
        // transformed path: per-row partials Σt, Σt², Σ t*gb
#pragma unroll
        for (int mt = 0; mt < 4; mt++)
#pragma unroll
            for (int h = 0; h < 2; h++) {
                int rloc = wm * 64 + mt * 16 + (lane >> 2) + h * 8;
                int j64  = (m0 + rloc) & (BASIS - 1);
                const float* gbrow = g_gb + j64 * D_DIM + n0 + wn * 32 + (lane & 3) * 2;
                float s = 0.f, s2 = 0.f, sbv = 0.f;
#pragma unroll
                for (int j = 0; j < 4; j++) {
                    float v0 = acc[mt][j][2 * h], v1 = acc[mt][j][2 * h + 1];
                    float gb0 = gbrow[j * 8], gb1 = gbrow[j * 8 + 1];
                    s  += v0 + v1;
                    s2 += v0 * v0 + v1 * v1;
                    sbv += v0 * gb0 + v1 * gb1;
                }
#pragma unroll
                for (int o = 1; o <= 2; o <<= 1) {
                    s   += __shfl_xor_sync(0xffffffffu, s, o);
                    s2  += __shfl_xor_sync(0xffffffffu, s2, o);
                    sbv += __shfl_xor_sync(0xffffffffu, sbv, o);
                }
                if ((lane & 3) == 0) {
                    atomicAdd(&sst[rloc * 3 + 0], s);
                    atomicAdd(&sst[rloc * 3 + 1], s2);
                    atomicAdd(&sst[rloc * 3 + 2], sbv);
                }
            }
        __syncthreads();
        if (tid < BM) {
            atomicAdd(&g_sum [m0 + tid], sst[tid * 3 + 0]);
            atomicAdd(&g_sum2[m0 + tid], sst[tid * 3 + 1]);
            atomicAdd(&g_dotb[m0 + tid], sst[tid * 3 + 2]);
        }
    }
}

// ---------------------------------------------------------------------------
__global__ void __launch_bounds__(256)
zero_stats_kernel() {
    int i = blockIdx.x * blockDim.x + threadIdx.x;
    if (i < M_TOT) { g_sum[i] = 0.f; g_sum2[i] = 0.f; g_dotb[i] = 0.f; }
}

__global__ void __launch_bounds__(256)
splitx_kernel(const float* __restrict__ src, int n4) {
    int i = blockIdx.x * blockDim.x + threadIdx.x;
    if (i >= n4) return;
    float4 v = ((const float4*)src)[i];
    __half h[4] = {__float2half_rn(v.x), __float2half_rn(v.y),
                   __float2half_rn(v.z), __float2half_rn(v.w)};
    *(uint2*)(g_xh + (size_t)i * 4) = *(uint2*)h;
}

__global__ void __launch_bounds__(256)
splitw_kernel(const float* __restrict__ src, __half* __restrict__ dst, int n4) {
    int i = blockIdx.x * blockDim.x + threadIdx.x;
    if (i >= n4) return;
    int row  = i / (K_DIM / 4);
    int col4 = i % (K_DIM / 4);
    float4 v = ((const float4*)src)[i];
    __half h[4] = {__float2half_rn(v.x), __float2half_rn(v.y),
                   __float2half_rn(v.z), __float2half_rn(v.w)};
    __half l[4] = {__float2half_rn(v.x - __half2float(h[0])),
                   __float2half_rn(v.y - __half2float(h[1])),
                   __float2half_rn(v.z - __half2float(h[2])),
                   __float2half_rn(v.w - __half2float(h[3]))};
    __half* rp = dst + (size_t)row * KC + col4 * 4;
    *(uint2*)(rp)         = *(uint2*)h;
    *(uint2*)(rp + K_DIM) = *(uint2*)l;
}

// gb[j][d] = gamma[d]*B[j][d]; c1[j] = sum gb; c2[j] = sum beta[d]*B[j][d]
__global__ void __launch_bounds__(256)
prep_kernel(const float* __restrict__ gamma, const float* __restrict__ beta,
            const float* __restrict__ Bb) {
    __shared__ float sh1[8], sh2[8];
    const int j = blockIdx.x, tid = threadIdx.x;
    float c1 = 0.f, c2 = 0.f;
    for (int d = tid; d < D_DIM; d += 256) {
        float b  = Bb[j * D_DIM + d];
        float gb = gamma[d] * b;
        g_gb[j * D_DIM + d] = gb;
        c1 += gb;
        c2 += beta[d] * b;
    }
#pragma unroll
    for (int o = 16; o > 0; o >>= 1) {
        c1 += __shfl_xor_sync(0xffffffffu, c1, o);
        c2 += __shfl_xor_sync(0xffffffffu, c2, o);
    }
    int lane = tid & 31, w = tid >> 5;
    if (lane == 0) { sh1[w] = c1; sh2[w] = c2; }
    __syncthreads();
    if (tid == 0) {
        float t1 = 0.f, t2 = 0.f;
#pragma unroll
        for (int i = 0; i < 8; i++) { t1 += sh1[i]; t2 += sh2[i]; }
        g_c1[j] = t1; g_c2[j] = t2;
    }
}

__global__ void __launch_bounds__(256)
transposeA_kernel(const float* __restrict__ Acoeff) {
    int idx = blockIdx.x * blockDim.x + threadIdx.x;
    if (idx < D_DIM * BASIS) {
        int d = idx / BASIS, j = idx % BASIS;
        g_At[j * D_DIM + d] = Acoeff[idx];
    }
}

__global__ void __launch_bounds__(256)
scalar_kernel() {
    int r = blockIdx.x * blockDim.x + threadIdx.x;
    if (r >= M_TOT) return;
    float mean = g_sum[r] * (1.0f / D_DIM);
    float var  = g_sum2[r] * (1.0f / D_DIM) - mean * mean;
    float inv  = rsqrtf(var + EPSV);
    int j = r & (BASIS - 1);
    g_scalar[r] = inv * (g_dotb[r] - mean * g_c1[j]) + g_c2[j];
}

__global__ void __launch_bounds__(256)
final_epilogue_kernel(float* __restrict__ out) {
    const int r = blockIdx.x;
    const int j = r & (BASIS - 1);
    const float sc = g_scalar[r];
    const int c0 = threadIdx.x * 8;
    const float* arow = g_At + j * D_DIM + c0;
    float* orow = out + (size_t)r * D_DIM + c0;
    float4 A0 = *(const float4*)(arow);
    float4 A1 = *(const float4*)(arow + 4);
    float4 o0 = *(const float4*)(orow);
    float4 o1 = *(const float4*)(orow + 4);
    o0.x += sc * A0.x;  o0.y += sc * A0.y;  o0.z += sc * A0.z;  o0.w += sc * A0.w;
    o1.x += sc * A1.x;  o1.y += sc * A1.y;  o1.z += sc * A1.z;  o1.w += sc * A1.w;
    *(float4*)(orow)     = o0;
    *(float4*)(orow + 4) = o1;
}

// ---------------------------------------------------------------------------
extern "C" void kernel_launch(void* const* d_in, const int* in_sizes, int n_in,
                              void* d_out, int out_size) {
    const float* x      = (const float*)d_in[0];
    const float* W      = (const float*)d_in[1];
    const float* W_res  = (const float*)d_in[2];
    const float* gamma  = (const float*)d_in[3];
    const float* beta   = (const float*)d_in[4];
    const float* Acoeff = (const float*)d_in[5];
    const float* Bbasis = (const float*)d_in[6];
    float* out = (float*)d_out;

    __half *xh; cudaGetSymbolAddress((void**)&xh, g_xh);
    __half *ws; cudaGetSymbolAddress((void**)&ws, g_ws);
    __half *rs; cudaGetSymbolAddress((void**)&rs, g_rs);

    cudaFuncSetAttribute(gemm_fused_kernel,
                         cudaFuncAttributeMaxDynamicSharedMemorySize, SM_TOTAL);

    zero_stats_kernel<<<(M_TOT + 255) / 256, 256>>>();
    prep_kernel<<<BASIS, 256>>>(gamma, beta, Bbasis);
    transposeA_kernel<<<(D_DIM * BASIS + 255) / 256, 256>>>(Acoeff);

    int nx4 = (M_TOT * K_DIM) / 4;
    int nw4 = (D_DIM * K_DIM) / 4;
    splitx_kernel<<<(nx4 + 255) / 256, 256>>>(x, nx4);
    splitw_kernel<<<(nw4 + 255) / 256, 256>>>(W, ws, nw4);
    splitw_kernel<<<(nw4 + 255) / 256, 256>>>(W_res, rs, nw4);

    dim3 grid(2 * D_DIM / BN, M_TOT / BM);   // (16, 128)
    gemm_fused_kernel<<<grid, NTHR, SM_TOTAL>>>(xh, ws, rs, out);

    scalar_kernel<<<(M_TOT + 255) / 256, 256>>>();
    final_epilogue_kernel<<<M_TOT, 256>>>(out);
}

// round 6
// speedup vs baseline: 9.1425x; 1.8273x over previous
#include <cuda_runtime.h>
#include <cuda_fp16.h>
#include <cstdint>

#define M_TOT 16384
#define K_DIM 2048
#define D_DIM 2048
#define BASIS 64
#define EPSV  1e-5f

#define BM     128
#define BN     256
#define BK     64
#define STAGES 3
#define NKT    (K_DIM / BK)    // 32
#define NTHR   512

// ---------------- scratch (__device__ globals) ------------------------------
__device__ __half g_xh[(size_t)M_TOT * K_DIM];   // 64MB
__device__ __half g_wh[(size_t)D_DIM * K_DIM];   // 8MB
__device__ __half g_rh[(size_t)D_DIM * K_DIM];   // 8MB
__device__ float  g_At[BASIS * D_DIM];
__device__ float  g_gb[BASIS * D_DIM];           // gamma[d]*B[j][d]
__device__ float  g_c1[BASIS], g_c2[BASIS];
__device__ float  g_sum[M_TOT], g_sum2[M_TOT], g_dotb[M_TOT];

// ---------------- PTX helpers ----------------------------------------------
__device__ __forceinline__ uint32_t smem_u32(const void* p) {
    uint32_t a;
    asm("{ .reg .u64 t; cvta.to.shared.u64 t, %1; cvt.u32.u64 %0, t; }" : "=r"(a) : "l"(p));
    return a;
}
__device__ __forceinline__ void cp_async16(uint32_t dst, const void* src) {
    asm volatile("cp.async.cg.shared.global [%0], [%1], 16;" :: "r"(dst), "l"(src));
}
__device__ __forceinline__ void cp_commit() {
    asm volatile("cp.async.commit_group;" ::: "memory");
}
template <int N>
__device__ __forceinline__ void cp_wait() {
    asm volatile("cp.async.wait_group %0;" :: "n"(N) : "memory");
}
__device__ __forceinline__ void ldsm4(uint32_t& r0, uint32_t& r1, uint32_t& r2,
                                      uint32_t& r3, uint32_t addr) {
    asm volatile("ldmatrix.sync.aligned.m8n8.x4.shared.b16 {%0,%1,%2,%3}, [%4];"
                 : "=r"(r0), "=r"(r1), "=r"(r2), "=r"(r3) : "r"(addr));
}
__device__ __forceinline__ void mma16816(float* d, uint32_t a0, uint32_t a1,
                                         uint32_t a2, uint32_t a3,
                                         uint32_t b0, uint32_t b1) {
    asm volatile("mma.sync.aligned.m16n8k16.row.col.f32.f16.f16.f32 "
                 "{%0,%1,%2,%3}, {%4,%5,%6,%7}, {%8,%9}, {%0,%1,%2,%3};"
                 : "+f"(d[0]), "+f"(d[1]), "+f"(d[2]), "+f"(d[3])
                 : "r"(a0), "r"(a1), "r"(a2), "r"(a3), "r"(b0), "r"(b1));
}

#define STAGE_BYTES (BM * 128 + BN * 128)           // 49152
#define SM_STATS    (STAGES * STAGE_BYTES)
#define SM_TOTAL    (STAGES * STAGE_BYTES + 1536)

// ---------------------------------------------------------------------------
// Fused dual GEMM. bsel=0: transformed path -> per-row LN partials only.
// bsel=1: residual path -> store tile to out. A = x (fp16), B = fp16 weights.
// ---------------------------------------------------------------------------
__global__ void __launch_bounds__(NTHR, 1)
gemm_fused_kernel(const __half* __restrict__ X,
                  const __half* __restrict__ Wh,
                  const __half* __restrict__ Rh,
                  float* __restrict__ out) {
    extern __shared__ char smem[];
    const uint32_t sb = smem_u32(smem);
    float* sst = (float*)(smem + SM_STATS);
    const int tid  = threadIdx.x;
    const int wid  = tid >> 5;
    const int lane = tid & 31;
    const int wm   = wid >> 3;           // 0..1
    const int wn   = wid & 7;            // 0..7
    const int m0   = blockIdx.y * BM;
    const int bsel = blockIdx.x >> 3;    // 0 = W (stats), 1 = W_res (store)
    const int n0   = (blockIdx.x & 7) * BN;
    const __half* Bmat = bsel ? Rh : Wh;

    if (tid < 384) sst[tid] = 0.f;       // first syncthreads is in iter 0

    auto load_stage = [&](int stage, int kt) {
        const uint32_t base = sb + stage * STAGE_BYTES;
        const int kb = kt * BK;
#pragma unroll
        for (int i = 0; i < 2; i++) {            // A: 1024 segs
            int seg = tid + i * NTHR;
            int r = seg >> 3, ch = seg & 7;
            cp_async16(base + r * 128 + ((ch ^ (r & 7)) << 4),
                       X + (size_t)(m0 + r) * K_DIM + kb + ch * 8);
        }
#pragma unroll
        for (int i = 0; i < 4; i++) {            // B: 2048 segs
            int seg = tid + i * NTHR;
            int r = seg >> 3, ch = seg & 7;
            cp_async16(base + BM * 128 + r * 128 + ((ch ^ (r & 7)) << 4),
                       Bmat + (size_t)(n0 + r) * K_DIM + kb + ch * 8);
        }
        cp_commit();
    };

    float acc[4][4][4];
#pragma unroll
    for (int i = 0; i < 4; i++)
#pragma unroll
        for (int j = 0; j < 4; j++)
#pragma unroll
            for (int q = 0; q < 4; q++) acc[i][j][q] = 0.f;

#pragma unroll
    for (int s = 0; s < STAGES - 1; s++) load_stage(s, s);

    for (int kt = 0; kt < NKT; kt++) {
        cp_wait<STAGES - 2>();
        __syncthreads();

        int tn = kt + STAGES - 1;
        if (tn < NKT) load_stage(tn % STAGES, tn);
        else          cp_commit();

        const uint32_t stA = sb + (kt % STAGES) * STAGE_BYTES;
        const uint32_t stB = stA + BM * 128;

#pragma unroll
        for (int s = 0; s < 4; s++) {
            uint32_t a[4][4];
#pragma unroll
            for (int mt = 0; mt < 4; mt++) {
                int r  = wm * 64 + mt * 16 + (lane & 15);
                int ch = 2 * s + (lane >> 4);
                ldsm4(a[mt][0], a[mt][1], a[mt][2], a[mt][3],
                      stA + r * 128 + ((ch ^ (r & 7)) << 4));
            }
            uint32_t b[2][4];
#pragma unroll
            for (int nt = 0; nt < 2; nt++) {
                int r  = wn * 32 + nt * 16 + (lane & 7) + ((lane >> 4) << 3);
                int ch = 2 * s + ((lane >> 3) & 1);
                ldsm4(b[nt][0], b[nt][1], b[nt][2], b[nt][3],
                      stB + r * 128 + ((ch ^ (r & 7)) << 4));
            }
#pragma unroll
            for (int mt = 0; mt < 4; mt++)
#pragma unroll
                for (int nt = 0; nt < 2; nt++) {
                    mma16816(acc[mt][2 * nt],     a[mt][0], a[mt][1], a[mt][2], a[mt][3],
                             b[nt][0], b[nt][1]);
                    mma16816(acc[mt][2 * nt + 1], a[mt][0], a[mt][1], a[mt][2], a[mt][3],
                             b[nt][2], b[nt][3]);
                }
        }
        __syncthreads();
    }

    if (bsel == 1) {
#pragma unroll
        for (int mt = 0; mt < 4; mt++) {
            int row  = m0 + wm * 64 + mt * 16 + (lane >> 2);
            int col0 = n0 + wn * 32 + (lane & 3) * 2;
#pragma unroll
            for (int j = 0; j < 4; j++) {
                *(float2*)(out + (size_t)row * D_DIM + col0 + j * 8) =
                    make_float2(acc[mt][j][0], acc[mt][j][1]);
                *(float2*)(out + (size_t)(row + 8) * D_DIM + col0 + j * 8) =
                    make_float2(acc[mt][j][2], acc[mt][j][3]);
            }
        }
    } else {
        // transformed path: per-row partials Σt, Σt², Σ t*gb
#pragma unroll
        for (int mt = 0; mt < 4; mt++)
#pragma unroll
            for (int h = 0; h < 2; h++) {
                int rloc = wm * 64 + mt * 16 + (lane >> 2) + h * 8;
                int j64  = (m0 + rloc) & (BASIS - 1);
                const float* gbrow = g_gb + j64 * D_DIM + n0 + wn * 32 + (lane & 3) * 2;
                float s = 0.f, s2 = 0.f, sbv = 0.f;
#pragma unroll
                for (int j = 0; j < 4; j++) {
                    float v0 = acc[mt][j][2 * h], v1 = acc[mt][j][2 * h + 1];
                    float gb0 = gbrow[j * 8], gb1 = gbrow[j * 8 + 1];
                    s  += v0 + v1;
                    s2 += v0 * v0 + v1 * v1;
                    sbv += v0 * gb0 + v1 * gb1;
                }
#pragma unroll
                for (int o = 1; o <= 2; o <<= 1) {
                    s   += __shfl_xor_sync(0xffffffffu, s, o);
                    s2  += __shfl_xor_sync(0xffffffffu, s2, o);
                    sbv += __shfl_xor_sync(0xffffffffu, sbv, o);
                }
                if ((lane & 3) == 0) {
                    atomicAdd(&sst[rloc * 3 + 0], s);
                    atomicAdd(&sst[rloc * 3 + 1], s2);
                    atomicAdd(&sst[rloc * 3 + 2], sbv);
                }
            }
        __syncthreads();
        if (tid < BM) {
            atomicAdd(&g_sum [m0 + tid], sst[tid * 3 + 0]);
            atomicAdd(&g_sum2[m0 + tid], sst[tid * 3 + 1]);
            atomicAdd(&g_dotb[m0 + tid], sst[tid * 3 + 2]);
        }
    }
}

// ---------------------------------------------------------------------------
__global__ void __launch_bounds__(256)
zero_stats_kernel() {
    int i = blockIdx.x * blockDim.x + threadIdx.x;
    if (i < M_TOT) { g_sum[i] = 0.f; g_sum2[i] = 0.f; g_dotb[i] = 0.f; }
}

__global__ void __launch_bounds__(256)
cvt_half_kernel(const float* __restrict__ src, __half* __restrict__ dst, int n4) {
    int i = blockIdx.x * blockDim.x + threadIdx.x;
    if (i >= n4) return;
    float4 v = ((const float4*)src)[i];
    __half h[4] = {__float2half_rn(v.x), __float2half_rn(v.y),
                   __float2half_rn(v.z), __float2half_rn(v.w)};
    *(uint2*)(dst + (size_t)i * 4) = *(uint2*)h;
}

// gb[j][d] = gamma[d]*B[j][d]; c1[j] = sum gb; c2[j] = sum beta[d]*B[j][d]
__global__ void __launch_bounds__(256)
prep_kernel(const float* __restrict__ gamma, const float* __restrict__ beta,
            const float* __restrict__ Bb) {
    __shared__ float sh1[8], sh2[8];
    const int j = blockIdx.x, tid = threadIdx.x;
    float c1 = 0.f, c2 = 0.f;
    for (int d = tid; d < D_DIM; d += 256) {
        float b  = Bb[j * D_DIM + d];
        float gb = gamma[d] * b;
        g_gb[j * D_DIM + d] = gb;
        c1 += gb;
        c2 += beta[d] * b;
    }
#pragma unroll
    for (int o = 16; o > 0; o >>= 1) {
        c1 += __shfl_xor_sync(0xffffffffu, c1, o);
        c2 += __shfl_xor_sync(0xffffffffu, c2, o);
    }
    int lane = tid & 31, w = tid >> 5;
    if (lane == 0) { sh1[w] = c1; sh2[w] = c2; }
    __syncthreads();
    if (tid == 0) {
        float t1 = 0.f, t2 = 0.f;
#pragma unroll
        for (int i = 0; i < 8; i++) { t1 += sh1[i]; t2 += sh2[i]; }
        g_c1[j] = t1; g_c2[j] = t2;
    }
}

__global__ void __launch_bounds__(256)
transposeA_kernel(const float* __restrict__ Acoeff) {
    int idx = blockIdx.x * blockDim.x + threadIdx.x;
    if (idx < D_DIM * BASIS) {
        int d = idx / BASIS, j = idx % BASIS;
        g_At[j * D_DIM + d] = Acoeff[idx];
    }
}

// scalar computed per block (row), then rank-1 add into out
__global__ void __launch_bounds__(256)
final_epilogue_kernel(float* __restrict__ out) {
    __shared__ float ssc;
    const int r = blockIdx.x;
    const int j = r & (BASIS - 1);
    if (threadIdx.x == 0) {
        float mean = g_sum[r] * (1.0f / D_DIM);
        float var  = g_sum2[r] * (1.0f / D_DIM) - mean * mean;
        float inv  = rsqrtf(var + EPSV);
        ssc = inv * (g_dotb[r] - mean * g_c1[j]) + g_c2[j];
    }
    __syncthreads();
    const float sc = ssc;
    const int c0 = threadIdx.x * 8;
    const float* arow = g_At + j * D_DIM + c0;
    float* orow = out + (size_t)r * D_DIM + c0;
    float4 A0 = *(const float4*)(arow);
    float4 A1 = *(const float4*)(arow + 4);
    float4 o0 = *(const float4*)(orow);
    float4 o1 = *(const float4*)(orow + 4);
    o0.x += sc * A0.x;  o0.y += sc * A0.y;  o0.z += sc * A0.z;  o0.w += sc * A0.w;
    o1.x += sc * A1.x;  o1.y += sc * A1.y;  o1.z += sc * A1.z;  o1.w += sc * A1.w;
    *(float4*)(orow)     = o0;
    *(float4*)(orow + 4) = o1;
}

// ---------------------------------------------------------------------------
extern "C" void kernel_launch(void* const* d_in, const int* in_sizes, int n_in,
                              void* d_out, int out_size) {
    const float* x      = (const float*)d_in[0];
    const float* W      = (const float*)d_in[1];
    const float* W_res  = (const float*)d_in[2];
    const float* gamma  = (const float*)d_in[3];
    const float* beta   = (const float*)d_in[4];
    const float* Acoeff = (const float*)d_in[5];
    const float* Bbasis = (const float*)d_in[6];
    float* out = (float*)d_out;

    __half *xh; cudaGetSymbolAddress((void**)&xh, g_xh);
    __half *wh; cudaGetSymbolAddress((void**)&wh, g_wh);
    __half *rh; cudaGetSymbolAddress((void**)&rh, g_rh);

    cudaFuncSetAttribute(gemm_fused_kernel,
                         cudaFuncAttributeMaxDynamicSharedMemorySize, SM_TOTAL);

    zero_stats_kernel<<<(M_TOT + 255) / 256, 256>>>();
    prep_kernel<<<BASIS, 256>>>(gamma, beta, Bbasis);
    transposeA_kernel<<<(D_DIM * BASIS + 255) / 256, 256>>>(Acoeff);

    int nx4 = (M_TOT * K_DIM) / 4;
    int nw4 = (D_DIM * K_DIM) / 4;
    cvt_half_kernel<<<(nx4 + 255) / 256, 256>>>(x, xh, nx4);
    cvt_half_kernel<<<(nw4 + 255) / 256, 256>>>(W, wh, nw4);
    cvt_half_kernel<<<(nw4 + 255) / 256, 256>>>(W_res, rh, nw4);

    dim3 grid(2 * D_DIM / BN, M_TOT / BM);   // (16, 128)
    gemm_fused_kernel<<<grid, NTHR, SM_TOTAL>>>(xh, wh, rh, out);

    final_epilogue_kernel<<<M_TOT, 256>>>(out);
}